// round 16
// baseline (speedup 1.0000x reference)
#include <cuda_runtime.h>
#include <cuda_bf16.h>
#include <cuda_fp16.h>
#include <cmath>
#include <cstdint>

#define BATCH 4
#define DIM   96
#define HEADS 6
#define HDIM  16
#define C3    288
#define HID   192
#define HID2  384
#define HW    65536
#define IMG   256

// conv3x3 mma tiling: chunk = 16 ic (= 8 u32 pair-words)
#define NCH3   18
#define BROW3  280
#define BSM3   (8 * 3 * BROW3)
#define WCH3   6912
#define WP3SZ  (3 * NCH3 * WCH3)
#define SMEM3  ((2 * BSM3 + 2 * WCH3) * 4)   // 109056 bytes

#define BRW    264

// ---------------- scratch ----------------
__device__ __align__(16) uint32_t g_xh   [(size_t)BATCH * 48 * HW];        // x bf16 ch-pair
__device__ __align__(16) uint32_t g_x2h  [(size_t)BATCH * 48 * HW];        // x2 bf16 ch-pair
__device__ __align__(16) uint32_t g_qkvh [(size_t)BATCH * (C3 / 2) * HW];  // qkv1 out, FP16 ch-pair
__device__ __align__(16) uint32_t g_qkpp [(size_t)BATCH * 192 * (HW / 2)]; // q,k px-pair bf16
__device__ __align__(16) uint32_t g_vcp  [(size_t)BATCH * 48 * HW];        // v ch-pair bf16
__device__ __align__(16) uint32_t g_t    [(size_t)BATCH * HID2 * HW / 2];  // pin out, px-pair bf16
__device__ __align__(16) uint32_t g_gw   [(size_t)BATCH * 96 * HW];        // dwgate out
__device__ float g_x2   [(size_t)BATCH * DIM * HW];
__device__ float g_wgs1 [C3];
__device__ float g_wb1  [C3];
__device__ float g_wgs2 [HID2];
__device__ float g_wb2  [HID2];
__device__ float g_sqk  [BATCH * 2 * DIM];
__device__ float g_attn [BATCH * HEADS * HDIM * HDIM];
__device__ __align__(16) uint32_t g_Wp1 [C3 * DIM / 2];
__device__ __align__(16) uint32_t g_Wp2 [HID2 * DIM / 2];
__device__ __align__(16) uint32_t g_Wpo [DIM * HID / 2];
__device__ __align__(16) uint32_t g_Mp  [BATCH * DIM * DIM / 2];
__device__ __align__(16) uint32_t g_Wp3 [WP3SZ];                           // FP16 conv3x3 weights

// ---------------- helpers ----------------
__device__ __forceinline__ void cpa16(uint32_t dst, const void* src) {
    asm volatile("cp.async.cg.shared.global [%0], [%1], 16;" :: "r"(dst), "l"(src));
}
__device__ __forceinline__ void cpa16z(uint32_t dst, const void* src, bool v) {
    asm volatile("cp.async.cg.shared.global [%0], [%1], 16, %2;"
                 :: "r"(dst), "l"(src), "r"(v ? 16u : 0u));
}
__device__ __forceinline__ uint32_t packbf(float lo, float hi) {
    uint32_t r;
    asm("cvt.rn.bf16x2.f32 %0, %1, %2;" : "=r"(r) : "f"(hi), "f"(lo));
    return r;
}
__device__ __forceinline__ uint32_t packhf(float lo, float hi) {
    uint32_t r;
    asm("cvt.rn.f16x2.f32 %0, %1, %2;" : "=r"(r) : "f"(hi), "f"(lo));
    return r;
}
__device__ __forceinline__ float2 unpackhf(uint32_t w) {
    __half2 h = *reinterpret_cast<__half2*>(&w);
    return __half22float2(h);
}
__device__ __forceinline__ void mma_bf16(float* c, const uint32_t* a,
                                         uint32_t b0, uint32_t b1) {
    asm volatile("mma.sync.aligned.m16n8k16.row.col.f32.bf16.bf16.f32 "
                 "{%0,%1,%2,%3}, {%4,%5,%6,%7}, {%8,%9}, {%0,%1,%2,%3};"
                 : "+f"(c[0]), "+f"(c[1]), "+f"(c[2]), "+f"(c[3])
                 : "r"(a[0]), "r"(a[1]), "r"(a[2]), "r"(a[3]), "r"(b0), "r"(b1));
}
// fp16 inputs, fp16 accumulators (halves register pressure)
__device__ __forceinline__ void mma_f16(uint32_t* c, const uint32_t* a,
                                        uint32_t b0, uint32_t b1) {
    asm volatile("mma.sync.aligned.m16n8k16.row.col.f16.f16.f16.f16 "
                 "{%0,%1}, {%2,%3,%4,%5}, {%6,%7}, {%0,%1};"
                 : "+r"(c[0]), "+r"(c[1])
                 : "r"(a[0]), "r"(a[1]), "r"(a[2]), "r"(a[3]), "r"(b0), "r"(b1));
}

// ---------------- fused setup: prep + 3 packs + zeros ----------------
#define S_PREP   (C3 + HID2)
#define S_P1     (C3 * DIM / 2)
#define S_P2     (HID2 * DIM / 2)
#define S_PO     (DIM * HID / 2)
#define S_ZA     (BATCH * HEADS * 256)
#define S_ZS     (BATCH * 2 * DIM)
#define S_TOTAL  (S_PREP + S_P1 + S_P2 + S_PO + S_ZA + S_ZS)

__device__ __forceinline__ void pack_pair(const float* W, const float* gamma,
                                          uint32_t* dst, int ICt, int idx) {
    int r = idx;
    int v = r & 3; r >>= 2;
    int lane = r & 31; r >>= 5;
    int mb = r % 3; r /= 3;
    int og = r % 2; r /= 2;
    int nch = ICt / 16;
    int ch = r % nch; r /= nch;
    int ocT = r;
    int g = lane >> 2, t = lane & 3;
    int oc = ocT * 96 + og * 48 + mb * 16 + g + (v & 1) * 8;
    int ic0 = ch * 16 + t + (v >> 1) * 4;
    float w0 = W[oc * ICt + ic0] * gamma[ic0];
    float w1 = W[oc * ICt + ic0 + 8] * gamma[ic0 + 8];
    dst[idx] = packbf(w0, w1);
}

__device__ __forceinline__ void pack_cons(const float* W, uint32_t* dst, int ICt, int idx) {
    int r = idx;
    int v = r & 3; r >>= 2;
    int lane = r & 31; r >>= 5;
    int mb = r % 3; r /= 3;
    int og = r % 2; r /= 2;
    int nch = ICt / 16;
    int ch = r % nch; r /= nch;
    int ocT = r;
    int g = lane >> 2, t = lane & 3;
    int oc = ocT * 96 + og * 48 + mb * 16 + g + (v & 1) * 8;
    int ic = ch * 16 + 2 * t + (v >> 1) * 8;
    dst[idx] = packbf(W[oc * ICt + ic], W[oc * ICt + ic + 1]);
}

__global__ void setup_kernel(const float* __restrict__ qkv1_w, const float* __restrict__ ln1_w,
                             const float* __restrict__ ln1_b, const float* __restrict__ pin_w,
                             const float* __restrict__ ln2_w, const float* __restrict__ ln2_b,
                             const float* __restrict__ pout_w) {
    int gid = blockIdx.x * 256 + threadIdx.x;
    if (gid < S_PREP) {
        int t = gid;
        if (t < C3) {
            float s = 0.f, sb = 0.f;
            for (int c = 0; c < DIM; c++) {
                float w = qkv1_w[t * DIM + c];
                s += w * ln1_w[c]; sb += w * ln1_b[c];
            }
            g_wgs1[t] = s; g_wb1[t] = sb;
        } else {
            int r = t - C3;
            float s = 0.f, sb = 0.f;
            for (int c = 0; c < DIM; c++) {
                float w = pin_w[r * DIM + c];
                s += w * ln2_w[c]; sb += w * ln2_b[c];
            }
            g_wgs2[r] = s; g_wb2[r] = sb;
        }
        return;
    }
    gid -= S_PREP;
    if (gid < S_P1) { pack_pair(qkv1_w, ln1_w, g_Wp1, DIM, gid); return; }
    gid -= S_P1;
    if (gid < S_P2) { pack_pair(pin_w, ln2_w, g_Wp2, DIM, gid); return; }
    gid -= S_P2;
    if (gid < S_PO) { pack_cons(pout_w, g_Wpo, HID, gid); return; }
    gid -= S_PO;
    if (gid < S_ZA) { g_attn[gid] = 0.f; return; }
    gid -= S_ZA;
    if (gid < S_ZS) { g_sqk[gid] = 0.f; return; }
}

// conv3x3 weights in FP16, (ic, ic+8) pairing
__global__ void pack3x3_kernel(const float* __restrict__ W) {
    int idx = blockIdx.x * 256 + threadIdx.x;
    if (idx >= WP3SZ) return;
    int r = idx;
    int v = r & 3; r >>= 2;
    int lane = r & 31; r >>= 5;
    int mb = r % 3; r /= 3;
    int kx = r % 3; r /= 3;
    int og = r % 2; r /= 2;
    int ky = r % 3; r /= 3;
    int ch = r % NCH3; r /= NCH3;
    int ocT = r;
    int g = lane >> 2, t = lane & 3;
    int oc = ocT * 96 + og * 48 + mb * 16 + g + (v & 1) * 8;
    int ic0 = ch * 16 + t + (v >> 1) * 4;
    float w0 = W[(oc * C3 + ic0) * 9 + ky * 3 + kx];
    float w1 = W[(oc * C3 + ic0 + 8) * 9 + ky * 3 + kx];
    g_Wp3[idx] = packhf(w0, w1);
}

// ---------------- x -> bf16 ch-pair convert ----------------
__global__ __launch_bounds__(256) void cvt_x_kernel(const float* __restrict__ x,
                                                    uint32_t* __restrict__ xh) {
    int idx = blockIdx.x * 256 + threadIdx.x;
    int b = idx / (48 * HW / 4);
    int rem = idx - b * (48 * HW / 4);
    int w = rem / (HW / 4);
    int p = (rem - w * (HW / 4)) * 4;
    int clo = (w >> 3) * 16 + (w & 7);
    const float* lo = x + ((size_t)b * DIM + clo) * HW + p;
    const float* hi = lo + (size_t)8 * HW;
    float4 l4 = *(const float4*)lo;
    float4 h4 = *(const float4*)hi;
    uint4 o;
    o.x = packbf(l4.x, h4.x); o.y = packbf(l4.y, h4.y);
    o.z = packbf(l4.z, h4.z); o.w = packbf(l4.w, h4.w);
    *(uint4*)&xh[((size_t)b * 48 + w) * HW + p] = o;
}

// ---------------- 1x1 conv, u32 ch-pair in, fused LN stats ----------------
// OMODE 1: FP16 ch-pair words out (feeds conv3x3). OMODE 2: bf16 px-pair out.
template <int ICW, int OMODE>
__global__ __launch_bounds__(256, 2) void conv1x1uln_kernel(
    const uint32_t* __restrict__ in,
    const uint32_t* __restrict__ Wp,
    const float* __restrict__ wgs, const float* __restrict__ wb,
    uint32_t* __restrict__ outv) {
    constexpr int NCH = ICW / 8;
    __shared__ __align__(16) uint32_t bsmw[2][8 * BRW];
    __shared__ __align__(16) uint32_t wsm[2][768];
    __shared__ float smu[256], srstd[256];

    int b = blockIdx.z, ocT = blockIdx.y, px0 = blockIdx.x * 256;
    int OCtot = gridDim.y * 96;
    int tid = threadIdx.x, warp = tid >> 5, lane = tid & 31;
    int og = warp >> 2, pg = warp & 3, g = lane >> 2, t = lane & 3;

    float acc[3][8][4];
#pragma unroll
    for (int mb = 0; mb < 3; mb++)
#pragma unroll
        for (int j = 0; j < 8; j++)
#pragma unroll
            for (int v = 0; v < 4; v++) acc[mb][j][v] = 0.f;

    float psum = 0.f, psq = 0.f;

    const uint32_t* Wb = Wp + (size_t)ocT * NCH * 768;
    auto issue = [&](int ch, int buf) {
#pragma unroll
        for (int k = 0; k < 2; k++) {
            int idx = tid + k * 256;
            int row = idx >> 6, c4 = idx & 63;
            const uint32_t* src = in + ((size_t)b * ICW + ch * 8 + row) * HW + px0 + c4 * 4;
            cpa16((uint32_t)__cvta_generic_to_shared(&bsmw[buf][row * BRW + c4 * 4]), src);
        }
        if (tid < 192)
            cpa16((uint32_t)__cvta_generic_to_shared(&wsm[buf][tid * 4]), Wb + ch * 768 + tid * 4);
        asm volatile("cp.async.commit_group;");
    };
    issue(0, 0);
    for (int s = 0; s < NCH; s++) {
        if (s + 1 < NCH) { issue(s + 1, (s + 1) & 1); asm volatile("cp.async.wait_group 1;"); }
        else asm volatile("cp.async.wait_group 0;");
        __syncthreads();
        int buf = s & 1;
        const uint32_t* bB = &bsmw[buf][0];
#pragma unroll
        for (int w = 0; w < 8; w++) {
            uint32_t word = bB[w * BRW + tid];
            __nv_bfloat162 bb = *reinterpret_cast<__nv_bfloat162*>(&word);
            float a0 = __bfloat162float(bb.x), a1 = __bfloat162float(bb.y);
            psum += a0 + a1; psq += a0 * a0 + a1 * a1;
        }
        const uint32_t* wc = &wsm[buf][og * 384];
        uint32_t a[3][4];
#pragma unroll
        for (int mb = 0; mb < 3; mb++) *(uint4*)a[mb] = *(const uint4*)&wc[mb * 128 + lane * 4];
#pragma unroll
        for (int j = 0; j < 8; j++) {
            int col = pg * 64 + 8 * j + g;
            uint32_t b0 = bB[t * BRW + col], b1 = bB[(t + 4) * BRW + col];
#pragma unroll
            for (int mb = 0; mb < 3; mb++) mma_bf16(acc[mb][j], a[mb], b0, b1);
        }
        __syncthreads();
    }

    {
        float mu = psum * (1.f / DIM);
        float var = psq * (1.f / DIM) - mu * mu;
        smu[tid] = mu;
        srstd[tid] = rsqrtf(var + 1e-5f);
    }
    __syncthreads();

#pragma unroll
    for (int mb = 0; mb < 3; mb++) {
        int oc = ocT * 96 + og * 48 + mb * 16 + g;
        float gs0 = wgs[oc], gs8 = wgs[oc + 8], bb0 = wb[oc], bb8 = wb[oc + 8];
#pragma unroll
        for (int j = 0; j < 8; j++) {
            int pl = pg * 64 + 8 * j + 2 * t;
            int px = px0 + pl;
            float m0 = smu[pl], m1 = smu[pl + 1], r0 = srstd[pl], r1 = srstd[pl + 1];
            float v00 = r0 * (acc[mb][j][0] - m0 * gs0) + bb0;
            float v01 = r1 * (acc[mb][j][1] - m1 * gs0) + bb0;
            float v10 = r0 * (acc[mb][j][2] - m0 * gs8) + bb8;
            float v11 = r1 * (acc[mb][j][3] - m1 * gs8) + bb8;
            if (OMODE == 1) {
                int ch = ocT * 6 + og * 3 + mb;
                int c2 = ch * 8 + g;
                uint2 val = make_uint2(packhf(v00, v10), packhf(v01, v11));
                *(uint2*)&outv[((size_t)b * (OCtot / 2) + c2) * HW + px] = val;
            } else {
                outv[(((size_t)b * OCtot + oc) * HW + px) >> 1] = packbf(v00, v01);
                outv[(((size_t)b * OCtot + oc + 8) * HW + px) >> 1] = packbf(v10, v11);
            }
        }
    }
}

// ---------------- 1x1 conv, u32 pair-word in, fp32 out + residual ----------------
template <int ICW, bool WH>
__global__ __launch_bounds__(256, 2) void conv1x1u_bmma_kernel(
    const uint32_t* __restrict__ in, int in_bstride,
    const uint32_t* __restrict__ Wp, int w_bstride,
    const float* __restrict__ res, float* __restrict__ out,
    uint32_t* __restrict__ outh) {
    constexpr int NCH = ICW / 8;
    __shared__ __align__(16) uint32_t bsmw[2][8 * BRW];
    __shared__ __align__(16) uint32_t wsm[2][768];
    int b = blockIdx.z, px0 = blockIdx.x * 256;
    int tid = threadIdx.x, warp = tid >> 5, lane = tid & 31;
    int og = warp >> 2, pg = warp & 3, g = lane >> 2, t = lane & 3;
    float acc[3][8][4];
#pragma unroll
    for (int mb = 0; mb < 3; mb++)
#pragma unroll
        for (int j = 0; j < 8; j++)
#pragma unroll
            for (int v = 0; v < 4; v++) acc[mb][j][v] = 0.f;
    const uint32_t* Wb = Wp + (size_t)b * w_bstride;
    auto issue = [&](int ch, int buf) {
#pragma unroll
        for (int k = 0; k < 2; k++) {
            int idx = tid + k * 256;
            int row = idx >> 6, c4 = idx & 63;
            const uint32_t* src = in + (size_t)b * in_bstride + (size_t)(ch * 8 + row) * HW + px0 + c4 * 4;
            cpa16((uint32_t)__cvta_generic_to_shared(&bsmw[buf][row * BRW + c4 * 4]), src);
        }
        if (tid < 192)
            cpa16((uint32_t)__cvta_generic_to_shared(&wsm[buf][tid * 4]), Wb + ch * 768 + tid * 4);
        asm volatile("cp.async.commit_group;");
    };
    issue(0, 0);
    for (int s = 0; s < NCH; s++) {
        if (s + 1 < NCH) { issue(s + 1, (s + 1) & 1); asm volatile("cp.async.wait_group 1;"); }
        else asm volatile("cp.async.wait_group 0;");
        __syncthreads();
        int buf = s & 1;
        const uint32_t* wc = &wsm[buf][og * 384];
        uint32_t a[3][4];
#pragma unroll
        for (int mb = 0; mb < 3; mb++) *(uint4*)a[mb] = *(const uint4*)&wc[mb * 128 + lane * 4];
        const uint32_t* bB = &bsmw[buf][0];
#pragma unroll
        for (int j = 0; j < 8; j++) {
            int col = pg * 64 + 8 * j + g;
            uint32_t b0 = bB[t * BRW + col], b1 = bB[(t + 4) * BRW + col];
#pragma unroll
            for (int mb = 0; mb < 3; mb++) mma_bf16(acc[mb][j], a[mb], b0, b1);
        }
        __syncthreads();
    }
#pragma unroll
    for (int mb = 0; mb < 3; mb++) {
        int oc = og * 48 + mb * 16 + g;
#pragma unroll
        for (int j = 0; j < 8; j++) {
            int px = px0 + pg * 64 + 8 * j + 2 * t;
            float2 ra = *(const float2*)&res[((size_t)b * 96 + oc) * HW + px];
            float2 rb = *(const float2*)&res[((size_t)b * 96 + oc + 8) * HW + px];
            float v00 = acc[mb][j][0] + ra.x, v01 = acc[mb][j][1] + ra.y;
            float v10 = acc[mb][j][2] + rb.x, v11 = acc[mb][j][3] + rb.y;
            *(float2*)&out[((size_t)b * 96 + oc) * HW + px] = make_float2(v00, v01);
            *(float2*)&out[((size_t)b * 96 + oc + 8) * HW + px] = make_float2(v10, v11);
            if (WH) {
                int w = (og * 3 + mb) * 8 + g;
                uint2 val = make_uint2(packbf(v00, v10), packbf(v01, v11));
                *(uint2*)&outh[((size_t)b * 48 + w) * HW + px] = val;
            }
        }
    }
}

// ---------------- conv3x3: fp16 mma with FP16 accumulators ----------------
__global__ __launch_bounds__(256, 2) void conv3x3_bmma_kernel(const uint32_t* __restrict__ in,
                                                              uint32_t* __restrict__ qk,
                                                              uint32_t* __restrict__ vout,
                                                              float* __restrict__ sqk) {
    extern __shared__ uint32_t dynsmem[];
    uint32_t* bsm = dynsmem;
    uint32_t* wsm = dynsmem + 2 * BSM3;

    int b = blockIdx.z, ocT = blockIdx.y, y = blockIdx.x;
    int tid = threadIdx.x, warp = tid >> 5, lane = tid & 31;
    int og = warp >> 2, pg = warp & 3, g = lane >> 2, t = lane & 3;

    if (tid < 96) {
        int s = tid;
        int side = s & 1; s >>= 1;
        int wr = s % 24; int bufi = s / 24;
        bsm[bufi * BSM3 + wr * BROW3 + (side ? 260 : 3)] = 0u;
    }

    uint32_t acc[3][8][2];            // fp16x2 accumulators: 48 regs
#pragma unroll
    for (int mb = 0; mb < 3; mb++)
#pragma unroll
        for (int j = 0; j < 8; j++) {
            acc[mb][j][0] = 0u; acc[mb][j][1] = 0u;
        }

    const uint32_t* wp_base = g_Wp3 + (size_t)ocT * NCH3 * WCH3;

    auto issue = [&](int ch, int buf) {
        const uint32_t* ibase = in + ((size_t)b * (C3 / 2) + ch * 8) * HW;
        uint32_t* bdst = bsm + buf * BSM3;
#pragma unroll
        for (int k = 0; k < 6; k++) {
            int idx = tid + k * 256;
            int wr = idx >> 6, c4 = idx & 63;
            int w = wr / 3, rr = wr - 3 * w;
            int gy = y + rr - 1;
            bool ok = (unsigned)gy < 256u;
            const uint32_t* src = ibase + (size_t)w * HW + (ok ? gy : 0) * IMG + c4 * 4;
            cpa16z((uint32_t)__cvta_generic_to_shared(bdst + wr * BROW3 + 4 + c4 * 4), src, ok);
        }
        const uint32_t* wsrc = wp_base + (size_t)ch * WCH3;
        uint32_t* wdst = wsm + buf * WCH3;
#pragma unroll
        for (int k = 0; k < 7; k++) {
            int i = tid + k * 256;
            if (i < WCH3 / 4)
                cpa16((uint32_t)__cvta_generic_to_shared(wdst + i * 4), wsrc + i * 4);
        }
        asm volatile("cp.async.commit_group;");
    };

    issue(0, 0);
    for (int s = 0; s < NCH3; s++) {
        if (s + 1 < NCH3) { issue(s + 1, (s + 1) & 1); asm volatile("cp.async.wait_group 1;"); }
        else asm volatile("cp.async.wait_group 0;");
        __syncthreads();
        int buf = s & 1;
        const uint32_t* bB = bsm + buf * BSM3;
        const uint32_t* wc = wsm + buf * WCH3;
        int colb = 3 + pg * 64 + g;
#pragma unroll
        for (int ky = 0; ky < 3; ky++) {
#pragma unroll
            for (int kx = 0; kx < 3; kx++) {
                const uint32_t* wbp = wc + (((ky * 2 + og) * 3 + kx) * 3) * 128;
                uint32_t a[3][4];
#pragma unroll
                for (int mb = 0; mb < 3; mb++)
                    *(uint4*)a[mb] = *(const uint4*)&wbp[mb * 128 + lane * 4];
#pragma unroll
                for (int j = 0; j < 8; j++) {
                    int col = colb + 8 * j + kx;
                    uint32_t b0 = bB[(t * 3 + ky) * BROW3 + col];
                    uint32_t b1 = bB[((t + 4) * 3 + ky) * BROW3 + col];
#pragma unroll
                    for (int mb = 0; mb < 3; mb++) mma_f16(acc[mb][j], a[mb], b0, b1);
                }
            }
        }
        __syncthreads();
    }

    if (ocT < 2) {
        // q,k: fused sum-of-squares + px-pair bf16 store
#pragma unroll
        for (int mb = 0; mb < 3; mb++) {
            float s0 = 0.f, s8 = 0.f;
            int oc = ocT * 96 + og * 48 + mb * 16 + g;
#pragma unroll
            for (int j = 0; j < 8; j++) {
                float2 f0 = unpackhf(acc[mb][j][0]);
                float2 f1 = unpackhf(acc[mb][j][1]);
                s0 += f0.x * f0.x + f0.y * f0.y;
                s8 += f1.x * f1.x + f1.y * f1.y;
                int px = pg * 64 + 8 * j + 2 * t;
                size_t base = (size_t)(b * 192 + oc) * (HW / 2) + ((y * IMG + px) >> 1);
                qk[base] = packbf(f0.x, f0.y);
                qk[base + (size_t)8 * (HW / 2)] = packbf(f1.x, f1.y);
            }
            s0 += __shfl_xor_sync(0xffffffffu, s0, 1);
            s0 += __shfl_xor_sync(0xffffffffu, s0, 2);
            s8 += __shfl_xor_sync(0xffffffffu, s8, 1);
            s8 += __shfl_xor_sync(0xffffffffu, s8, 2);
            if (t == 0) {
                atomicAdd(&sqk[b * 2 * DIM + oc], s0);
                atomicAdd(&sqk[b * 2 * DIM + oc + 8], s8);
            }
        }
    } else {
        // v: channel-pair bf16 words (oc, oc+8)
#pragma unroll
        for (int mb = 0; mb < 3; mb++) {
            int c2 = (og * 3 + mb) * 8 + g;
#pragma unroll
            for (int j = 0; j < 8; j++) {
                float2 f0 = unpackhf(acc[mb][j][0]);
                float2 f1 = unpackhf(acc[mb][j][1]);
                int px = pg * 64 + 8 * j + 2 * t;
                uint2 val = make_uint2(packbf(f0.x, f1.x), packbf(f0.y, f1.y));
                *(uint2*)&vout[((size_t)(b * 48 + c2)) * HW + y * IMG + px] = val;
            }
        }
    }
}

// ---------------- attention gram ----------------
__global__ __launch_bounds__(256) void attn_bmma_kernel(const uint32_t* __restrict__ qk,
                                                        float* __restrict__ attn_raw) {
    int bh = blockIdx.y;
    int b = bh / HEADS, h = bh - b * HEADS;
    int warp = threadIdx.x >> 5, lane = threadIdx.x & 31;
    int tg = lane >> 2, t = lane & 3;
    const uint32_t* q0 = qk + (size_t)(b * 192 + h * HDIM + tg) * (HW / 2);
    const uint32_t* q1 = q0 + (size_t)8 * (HW / 2);
    const uint32_t* k0 = qk + (size_t)(b * 192 + 96 + h * HDIM + tg) * (HW / 2);
    const uint32_t* k1 = k0 + (size_t)8 * (HW / 2);
    float c0[4] = {0.f, 0.f, 0.f, 0.f};
    float c1[4] = {0.f, 0.f, 0.f, 0.f};
    int slab0 = (blockIdx.x * 8 + warp) * 16;
    for (int s = 0; s < 16; s++) {
        int w0 = (slab0 + s) * 32 + 4 * t;
        uint32_t qa[4], qb[4], qc[4], qd[4], ka[4], kc[4], kb[4], kd[4];
        *(uint4*)qa = *(const uint4*)(q0 + w0);
        *(uint4*)qb = *(const uint4*)(q1 + w0);
        *(uint4*)qc = *(const uint4*)(q0 + w0 + 16);
        *(uint4*)qd = *(const uint4*)(q1 + w0 + 16);
        *(uint4*)ka = *(const uint4*)(k0 + w0);
        *(uint4*)kc = *(const uint4*)(k0 + w0 + 16);
        *(uint4*)kb = *(const uint4*)(k1 + w0);
        *(uint4*)kd = *(const uint4*)(k1 + w0 + 16);
#pragma unroll
        for (int m = 0; m < 4; m++) {
            uint32_t a[4] = { qa[m], qb[m], qc[m], qd[m] };
            mma_bf16(c0, a, ka[m], kc[m]);
            mma_bf16(c1, a, kb[m], kd[m]);
        }
    }
    float* dst = attn_raw + bh * 256;
    atomicAdd(dst + tg * 16 + 2 * t, c0[0]);
    atomicAdd(dst + tg * 16 + 2 * t + 1, c0[1]);
    atomicAdd(dst + (tg + 8) * 16 + 2 * t, c0[2]);
    atomicAdd(dst + (tg + 8) * 16 + 2 * t + 1, c0[3]);
    atomicAdd(dst + tg * 16 + 8 + 2 * t, c1[0]);
    atomicAdd(dst + tg * 16 + 8 + 2 * t + 1, c1[1]);
    atomicAdd(dst + (tg + 8) * 16 + 8 + 2 * t, c1[2]);
    atomicAdd(dst + (tg + 8) * 16 + 8 + 2 * t + 1, c1[3]);
}

// ---------------- softmax + fused M ----------------
__global__ __launch_bounds__(256) void softmax_build_M(const float* __restrict__ attn_raw,
                                                       const float* __restrict__ sqk,
                                                       const float* __restrict__ scale,
                                                       const float* __restrict__ proj_w,
                                                       uint32_t* __restrict__ Mp) {
    int b = blockIdx.x;
    int tdx = threadIdx.x;
    __shared__ float A[HEADS * 256];
    __shared__ float nq[DIM], nk[DIM];
    if (tdx < DIM) {
        nq[tdx] = fmaxf(sqrtf(sqk[b * 2 * DIM + tdx]), 1e-12f);
        nk[tdx] = fmaxf(sqrtf(sqk[b * 2 * DIM + DIM + tdx]), 1e-12f);
    }
    __syncthreads();
    for (int idx = tdx; idx < HEADS * 256; idx += 256) {
        int h = idx >> 8;
        int cd = idx & 255;
        int c = cd >> 4, d = cd & 15;
        A[idx] = attn_raw[b * HEADS * 256 + idx] /
                 (nq[h * HDIM + c] * nk[h * HDIM + d]) * scale[h];
    }
    __syncthreads();
    if (tdx < DIM) {
        int h = tdx >> 4, c = tdx & 15;
        float* row = &A[h * 256 + c * 16];
        float mx = row[0];
#pragma unroll
        for (int d = 1; d < 16; d++) mx = fmaxf(mx, row[d]);
        float sum = 0.f;
#pragma unroll
        for (int d = 0; d < 16; d++) { float e = expf(row[d] - mx); row[d] = e; sum += e; }
        float inv = 1.f / sum;
#pragma unroll
        for (int d = 0; d < 16; d++) row[d] *= inv;
    }
    __syncthreads();
    for (int idx = tdx; idx < DIM * DIM / 2; idx += 256) {
        int r = idx;
        int v = r & 3; r >>= 2;
        int lane = r & 31; r >>= 5;
        int mb = r % 3; r /= 3;
        int og = r % 2; r /= 2;
        int ch = r;
        int g = lane >> 2, t = lane & 3;
        int oc = og * 48 + mb * 16 + g + (v & 1) * 8;
        int d = t + (v >> 1) * 4;
        int h = ch;
        float s0 = 0.f, s1 = 0.f;
#pragma unroll
        for (int cg = 0; cg < 16; cg++) {
            float pw = proj_w[oc * DIM + h * HDIM + cg];
            s0 += pw * A[h * 256 + cg * 16 + d];
            s1 += pw * A[h * 256 + cg * 16 + d + 8];
        }
        Mp[b * (DIM * DIM / 2) + idx] = packbf(s0, s1);
    }
}

// ---------------- dwconv + gate (LDG-direct, 8 px/thread) ----------------
__device__ __forceinline__ float gelu_tanh(float x) {
    float x3 = x * x * x;
    return 0.5f * x * (1.f + tanhf(0.7978845608028654f * (x + 0.044715f * x3)));
}

__global__ __launch_bounds__(256) void dwgate_kernel(const uint32_t* __restrict__ tin,
                                                     const float* __restrict__ dw,
                                                     uint32_t* __restrict__ gw) {
    int b = blockIdx.z, m = blockIdx.y;
    int y = blockIdx.x * 8 + (threadIdx.x >> 5);
    int px0 = (threadIdx.x & 31) * 8;
    int tid = threadIdx.x;

    __shared__ float swt[72];
    int chans[4] = {2 * m, 2 * m + 1, HID + 2 * m, HID + 2 * m + 1};
    if (tid < 72) {
        int oci = tid / 18;
        swt[tid] = dw[(size_t)chans[oci] * 18 + (tid - oci * 18)];
    }
    __syncthreads();

    float u[4][8];
#pragma unroll
    for (int ol = 0; ol < 4; ol++)
#pragma unroll
        for (int j = 0; j < 8; j++) u[ol][j] = 0.f;

    int wbase = px0 >> 1;
#pragma unroll
    for (int ic = 0; ic < 4; ic++) {
        const uint32_t* chb = tin + ((size_t)(b * HID2 + chans[ic]) * HW) / 2;
        int olb = (ic >> 1) << 1;
        int wi0 = (ic & 1) * 9;
#pragma unroll
        for (int ky = 0; ky < 3; ky++) {
            int gy = y + ky - 1;
            bool rok = (unsigned)gy < 256u;
            const uint32_t* rowp = chb + gy * 128;
            float v[12];
#pragma unroll
            for (int w = 0; w < 6; w++) {
                int wi = wbase - 1 + w;
                uint32_t word = (rok && (unsigned)wi < 128u) ? __ldg(rowp + wi) : 0u;
                __nv_bfloat162 bb = *reinterpret_cast<__nv_bfloat162*>(&word);
                v[2 * w] = __bfloat162float(bb.x);
                v[2 * w + 1] = __bfloat162float(bb.y);
            }
#pragma unroll
            for (int kx = 0; kx < 3; kx++) {
                float w0 = swt[olb * 18 + wi0 + ky * 3 + kx];
                float w1 = swt[(olb + 1) * 18 + wi0 + ky * 3 + kx];
#pragma unroll
                for (int j = 0; j < 8; j++) {
                    float xv = v[j + kx + 1];
                    u[olb][j] += w0 * xv;
                    u[olb + 1][j] += w1 * xv;
                }
            }
        }
    }

    uint32_t outw[8];
#pragma unroll
    for (int j = 0; j < 8; j++)
        outw[j] = packbf(gelu_tanh(u[0][j]) * u[2][j], gelu_tanh(u[1][j]) * u[3][j]);
    uint32_t* dst = gw + ((size_t)b * 96 + m) * HW + y * IMG + px0;
    *(uint4*)dst = *(uint4*)&outw[0];
    *(uint4*)(dst + 4) = *(uint4*)&outw[4];
}

// ---------------- launch ----------------
static void* sym_addr(const void* sym) {
    void* p = nullptr;
    cudaGetSymbolAddress(&p, sym);
    return p;
}

extern "C" void kernel_launch(void* const* d_in, const int* in_sizes, int n_in,
                              void* d_out, int out_size) {
    const float* x      = (const float*)d_in[0];
    const float* ln1_w  = (const float*)d_in[1];
    const float* ln1_b  = (const float*)d_in[2];
    const float* qkv1_w = (const float*)d_in[3];
    const float* qkv2_w = (const float*)d_in[4];
    const float* proj_w = (const float*)d_in[5];
    const float* scale  = (const float*)d_in[6];
    const float* ln2_w  = (const float*)d_in[7];
    const float* ln2_b  = (const float*)d_in[8];
    const float* pin_w  = (const float*)d_in[9];
    const float* dw_w   = (const float*)d_in[10];
    const float* pout_w = (const float*)d_in[11];

    uint32_t* xh   = (uint32_t*)sym_addr(g_xh);
    uint32_t* x2h  = (uint32_t*)sym_addr(g_x2h);
    uint32_t* qkvh = (uint32_t*)sym_addr(g_qkvh);
    uint32_t* qkpp = (uint32_t*)sym_addr(g_qkpp);
    uint32_t* vcp  = (uint32_t*)sym_addr(g_vcp);
    uint32_t* tbuf = (uint32_t*)sym_addr(g_t);
    uint32_t* gw   = (uint32_t*)sym_addr(g_gw);
    float* x2   = (float*)sym_addr(g_x2);
    float* wgs1 = (float*)sym_addr(g_wgs1);
    float* wb1  = (float*)sym_addr(g_wb1);
    float* wgs2 = (float*)sym_addr(g_wgs2);
    float* wb2  = (float*)sym_addr(g_wb2);
    float* sqk  = (float*)sym_addr(g_sqk);
    float* attn = (float*)sym_addr(g_attn);
    uint32_t* Wp1 = (uint32_t*)sym_addr(g_Wp1);
    uint32_t* Wp2 = (uint32_t*)sym_addr(g_Wp2);
    uint32_t* Wpo = (uint32_t*)sym_addr(g_Wpo);
    uint32_t* Mp  = (uint32_t*)sym_addr(g_Mp);
    float* out = (float*)d_out;

    static bool attr_done = false;
    if (!attr_done) {
        cudaFuncSetAttribute(conv3x3_bmma_kernel,
                             cudaFuncAttributeMaxDynamicSharedMemorySize, SMEM3);
        attr_done = true;
    }

    setup_kernel<<<(S_TOTAL + 255) / 256, 256>>>(qkv1_w, ln1_w, ln1_b,
                                                 pin_w, ln2_w, ln2_b, pout_w);
    pack3x3_kernel<<<(WP3SZ + 255) / 256, 256>>>(qkv2_w);

    cvt_x_kernel<<<BATCH * 48 * HW / 4 / 256, 256>>>(x, xh);
    conv1x1uln_kernel<48, 1><<<dim3(256, 3, BATCH), 256>>>(
        xh, Wp1, wgs1, wb1, qkvh);

    conv3x3_bmma_kernel<<<dim3(256, 3, BATCH), 256, SMEM3>>>(qkvh, qkpp, vcp, sqk);

    attn_bmma_kernel<<<dim3(8, BATCH * HEADS), 256>>>(qkpp, attn);
    softmax_build_M<<<BATCH, 256>>>(attn, sqk, scale, proj_w, Mp);

    conv1x1u_bmma_kernel<48, true><<<dim3(256, 1, BATCH), 256>>>(
        vcp, 48 * HW, Mp, DIM * DIM / 2, x, x2, x2h);

    conv1x1uln_kernel<48, 2><<<dim3(256, 4, BATCH), 256>>>(
        x2h, Wp2, wgs2, wb2, tbuf);

    dwgate_kernel<<<dim3(32, DIM, BATCH), 256>>>(tbuf, dw_w, gw);

    conv1x1u_bmma_kernel<96, false><<<dim3(256, 1, BATCH), 256>>>(
        gw, 96 * HW, Wpo, 0, x2, out, nullptr);
}